// round 2
// baseline (speedup 1.0000x reference)
#include <cuda_runtime.h>
#include <math.h>

#define NN   100000
#define NE   800000
#define FIN  128
#define C    32
#define D    16
#define CST  1e-5f

// ---------- persistent scratch (device globals; no allocation allowed) ----------
__device__ float  g_Q[NN * C];                 // 12.8 MB
__device__ float  g_Kbuf[2][NN * C];           // 25.6 MB
__device__ float4 g_M[2][NN * (C * D / 4)];    // 2 x 204.8 MB  (row = 128 float4)
__device__ int    g_deg[NN];
__device__ int    g_off[NN + 1];
__device__ int    g_cur[NN];
__device__ int    g_adj[NE];
__device__ int    g_is64;

// ------------------------------------------------- edge dtype detection -------
// Reads the first 16 values as int64 (128 bytes: in-bounds for both layouts).
// int64 edge data: all values in [0, n). int32 data read as int64: high word
// holds the NEXT index, which is nonzero with overwhelming probability.
__global__ void detect_kernel(const void* __restrict__ ei, int n) {
    const long long* p = (const long long*)ei;
    int ok = 1;
    for (int i = 0; i < 16; i++) {
        long long v = p[i];
        if (v < 0 || v >= (long long)n) ok = 0;
    }
    g_is64 = ok;
}

// ---------------------------------------------------------------- CSR build ---
__global__ void zero_deg_kernel(int n) {
    for (int i = blockIdx.x * blockDim.x + threadIdx.x; i < n; i += gridDim.x * blockDim.x)
        g_deg[i] = 0;
}

__global__ void count_kernel(const void* __restrict__ ei, int ne) {
    const long long* p64 = (const long long*)ei;
    const int*       p32 = (const int*)ei;
    int is64 = g_is64;
    for (int e = blockIdx.x * blockDim.x + threadIdx.x; e < ne; e += gridDim.x * blockDim.x) {
        int c = is64 ? (int)p64[ne + e] : p32[ne + e];   // col (destination)
        atomicAdd(&g_deg[c], 1);
    }
}

// single-block scan: 1024 threads, each owns a contiguous chunk
__global__ void scan_kernel(int n) {
    __shared__ int s[1024];
    int tid   = threadIdx.x;
    int chunk = (n + 1023) >> 10;
    int b = tid * chunk;
    int e = min(b + chunk, n);
    int sum = 0;
    for (int i = b; i < e; i++) sum += g_deg[i];
    s[tid] = sum;
    __syncthreads();
    // inclusive Hillis-Steele
    for (int off = 1; off < 1024; off <<= 1) {
        int v = (tid >= off) ? s[tid - off] : 0;
        __syncthreads();
        s[tid] += v;
        __syncthreads();
    }
    int run = s[tid] - sum;  // exclusive prefix for this chunk
    for (int i = b; i < e; i++) {
        g_off[i] = run;
        g_cur[i] = run;
        run += g_deg[i];
    }
    if (tid == 1023) g_off[n] = s[1023];
}

__global__ void scatter_kernel(const void* __restrict__ ei, int ne) {
    const long long* p64 = (const long long*)ei;
    const int*       p32 = (const int*)ei;
    int is64 = g_is64;
    for (int e = blockIdx.x * blockDim.x + threadIdx.x; e < ne; e += gridDim.x * blockDim.x) {
        int c = is64 ? (int)p64[ne + e] : p32[ne + e];
        int r = is64 ? (int)p64[e]      : p32[e];
        int p = atomicAdd(&g_cur[c], 1);
        g_adj[p] = r;
    }
}

// -------------------------------------------------------- front-end (fused) ---
// x = relu(feat @ Win + bin); Q = 1+elu(x@Wq+bq); K = 1+elu(x@Wk+bk); V = x@Wv+bv
// M0 = K outer V; hidden = hopwise[0] * V
// one warp per node, 8 nodes per 256-thread block; weights staged in SMEM
__global__ void feat_kernel(const float* __restrict__ feat,
                            const float* __restrict__ Win, const float* __restrict__ bin,
                            const float* __restrict__ Wq,  const float* __restrict__ bq,
                            const float* __restrict__ Wk,  const float* __restrict__ bk,
                            const float* __restrict__ Wv,  const float* __restrict__ bv,
                            const float* __restrict__ hopwise,
                            float* __restrict__ out, int n) {
    __shared__ float sWin[FIN * C];
    __shared__ float sWq[C * C], sWk[C * C], sWv[C * D];
    __shared__ float sb[3 * C + D];
    __shared__ float sx [8][FIN];
    __shared__ float sxs[8][C];

    int tid = threadIdx.x;
    for (int i = tid; i < FIN * C; i += 256) sWin[i] = Win[i];
    for (int i = tid; i < C * C;   i += 256) { sWq[i] = Wq[i]; sWk[i] = Wk[i]; }
    for (int i = tid; i < C * D;   i += 256) sWv[i] = Wv[i];
    if (tid < C) { sb[tid] = bin[tid]; sb[C + tid] = bq[tid]; sb[2 * C + tid] = bk[tid]; }
    if (tid < D) sb[3 * C + tid] = bv[tid];
    __syncthreads();

    int w = tid >> 5, lane = tid & 31;
    int node = blockIdx.x * 8 + w;
    if (node >= n) return;

    // stage feature row in SMEM
    ((float4*)sx[w])[lane] = ((const float4*)feat)[node * (FIN / 4) + lane];
    __syncwarp();

    float acc = sb[lane];
#pragma unroll 8
    for (int i = 0; i < FIN; i++) acc = fmaf(sx[w][i], sWin[i * C + lane], acc);
    float x = fmaxf(acc, 0.f);
    sxs[w][lane] = x;
    __syncwarp();

    float qz = sb[C + lane], kz = sb[2 * C + lane];
    float vz = (lane < D) ? sb[3 * C + lane] : 0.f;
#pragma unroll
    for (int i = 0; i < C; i++) {
        float xi = sxs[w][i];
        qz = fmaf(xi, sWq[i * C + lane], qz);
        kz = fmaf(xi, sWk[i * C + lane], kz);
        if (lane < D) vz = fmaf(xi, sWv[i * D + lane], vz);
    }
    float q = (qz > 0.f) ? 1.f + qz : expf(qz);  // 1 + elu
    float k = (kz > 0.f) ? 1.f + kz : expf(kz);

    g_Q[node * C + lane]       = q;
    g_Kbuf[0][node * C + lane] = k;

    float hw0 = hopwise[0];
    if (lane < D) out[node * D + lane] = hw0 * vz;

    // M0[node][i=lane][j] = k * V[j]; row layout: 128 float4, thread covers 4t..4t+3
    float4* mrow = &g_M[0][(size_t)node * (C * D / 4)];
#pragma unroll
    for (int b4 = 0; b4 < 4; b4++) {
        float v0 = __shfl_sync(0xffffffffu, vz, b4 * 4 + 0);
        float v1 = __shfl_sync(0xffffffffu, vz, b4 * 4 + 1);
        float v2 = __shfl_sync(0xffffffffu, vz, b4 * 4 + 2);
        float v3 = __shfl_sync(0xffffffffu, vz, b4 * 4 + 3);
        mrow[lane * 4 + b4] = make_float4(k * v0, k * v1, k * v2, k * v3);
    }
}

// ------------------------------------------------------------- fused hop ------
// per dst node: aggregate M,K over in-neighbors (CSR gather), then
// H = Q . M_new (contract over c), Cden = Q . K_new + CST, hidden += hw * H/Cden
// 128 threads/block: thread t owns M float4 index t (cols 4t..4t+3)
__global__ void hop_kernel(float* __restrict__ out,
                           const float* __restrict__ hopwise,
                           int hop, int src, int writeM) {
    const float4* __restrict__ Mold = g_M[src];
    float4*       __restrict__ Mnew = g_M[src ^ 1];
    const float*  __restrict__ Kold = g_Kbuf[src];
    float*        __restrict__ Knew = g_Kbuf[src ^ 1];

    int c = blockIdx.x;
    int t = threadIdx.x;            // 0..127
    int start = g_off[c], end = g_off[c + 1];

    float4 acc = make_float4(0.f, 0.f, 0.f, 0.f);
    float  kacc = 0.f;
    for (int e = start; e < end; e++) {
        int r = g_adj[e];
        float4 m = Mold[(size_t)r * 128 + t];
        acc.x += m.x; acc.y += m.y; acc.z += m.z; acc.w += m.w;
        if (t < 32) kacc += Kold[r * 32 + t];
    }
    if (writeM) {
        Mnew[(size_t)c * 128 + t] = acc;
        if (t < 32) Knew[c * 32 + t] = kacc;
    }

    // H partials: i = t>>2 (row of M), j-group g = t&3 (cols g*4..g*4+3)
    int i = t >> 2;
    float qi = g_Q[c * 32 + i];
    float h0 = qi * acc.x, h1 = qi * acc.y, h2 = qi * acc.z, h3 = qi * acc.w;
#pragma unroll
    for (int off = 4; off <= 16; off <<= 1) {
        h0 += __shfl_xor_sync(0xffffffffu, h0, off);
        h1 += __shfl_xor_sync(0xffffffffu, h1, off);
        h2 += __shfl_xor_sync(0xffffffffu, h2, off);
        h3 += __shfl_xor_sync(0xffffffffu, h3, off);
    }

    __shared__ float sH[4][4][4];   // [warp][jgroup][k]
    __shared__ float sC;
    int lane = t & 31, w = t >> 5;
    if (lane < 4) { sH[w][lane][0] = h0; sH[w][lane][1] = h1; sH[w][lane][2] = h2; sH[w][lane][3] = h3; }
    if (t < 32) {  // warp 0 holds kacc
        float cp = g_Q[c * 32 + t] * kacc;
#pragma unroll
        for (int off = 16; off >= 1; off >>= 1) cp += __shfl_xor_sync(0xffffffffu, cp, off);
        if (t == 0) sC = cp;
    }
    __syncthreads();

    if (t < 16) {
        float H = sH[0][t >> 2][t & 3] + sH[1][t >> 2][t & 3]
                + sH[2][t >> 2][t & 3] + sH[3][t >> 2][t & 3];
        float hw = hopwise[hop + 1];
        out[c * 16 + t] += hw * H / (sC + CST);
    }
}

// ------------------------------------------------------------------ launch ----
extern "C" void kernel_launch(void* const* d_in, const int* in_sizes, int n_in,
                              void* d_out, int out_size) {
    const float* feat    = (const float*)d_in[0];
    const void*  ei      = d_in[1];
    const float* Win     = (const float*)d_in[2];
    const float* bin     = (const float*)d_in[3];
    const float* Wq      = (const float*)d_in[4];
    const float* bq      = (const float*)d_in[5];
    const float* Wk      = (const float*)d_in[6];
    const float* bk      = (const float*)d_in[7];
    const float* Wv      = (const float*)d_in[8];
    const float* bv      = (const float*)d_in[9];
    const float* hopwise = (const float*)d_in[10];
    float*       out     = (float*)d_out;

    int n  = in_sizes[0] / FIN;   // 100000
    int ne = in_sizes[1] / 2;     // 800000

    // detect int32 vs int64 edge indices, then CSR build (by destination)
    detect_kernel<<<1, 1>>>(ei, n);
    zero_deg_kernel<<<256, 256>>>(n);
    count_kernel<<<1024, 256>>>(ei, ne);
    scan_kernel<<<1, 1024>>>(n);
    scatter_kernel<<<1024, 256>>>(ei, ne);

    // front-end: x, Q, K0, V, M0, hidden init
    feat_kernel<<<(n + 7) / 8, 256>>>(feat, Win, bin, Wq, bq, Wk, bk, Wv, bv,
                                      hopwise, out, n);

    // 3 hops; last hop skips M/K writeback
    int src = 0;
    for (int hop = 0; hop < 3; hop++) {
        hop_kernel<<<n, 128>>>(out, hopwise, hop, src, hop < 2 ? 1 : 0);
        src ^= 1;
    }
}

// round 3
// speedup vs baseline: 1.5312x; 1.5312x over previous
#include <cuda_runtime.h>
#include <cuda_fp16.h>
#include <math.h>

#define NN   100000
#define NE   800000
#define FIN  128
#define C    32
#define D    16
#define CST  1e-5f

// ---------- persistent scratch (device globals; no allocation allowed) ----------
__device__ float  g_Q[NN * C];                  // 12.8 MB
__device__ float  g_Kbuf[2][NN * C];            // 25.6 MB
__device__ __half g_Mh[2][NN * C * D];          // 2 x 102.4 MB (row = 512 halfs)
__device__ int    g_deg[NN];
__device__ int    g_off[NN + 1];
__device__ int    g_cur[NN];
__device__ int    g_adj[NE];
__device__ int    g_bsum[1024];
__device__ int    g_bpre[1024];
__device__ int    g_is64;

// ------------------------------------------------- edge dtype detection -------
// int64 edge data: first 16 int64 reads all land in [0, n). int32 data read as
// int64 has the NEXT index in the high word -> out of range w.h.p.
__global__ void detect_kernel(const void* __restrict__ ei, int n) {
    const long long* p = (const long long*)ei;
    int ok = 1;
    for (int i = 0; i < 16; i++) {
        long long v = p[i];
        if (v < 0 || v >= (long long)n) ok = 0;
    }
    g_is64 = ok;
}

// ---------------------------------------------------------------- CSR build ---
__global__ void zero_deg_kernel(int n) {
    for (int i = blockIdx.x * blockDim.x + threadIdx.x; i < n; i += gridDim.x * blockDim.x)
        g_deg[i] = 0;
}

__global__ void count_kernel(const void* __restrict__ ei, int ne) {
    const long long* p64 = (const long long*)ei;
    const int*       p32 = (const int*)ei;
    int is64 = g_is64;
    for (int e = blockIdx.x * blockDim.x + threadIdx.x; e < ne; e += gridDim.x * blockDim.x) {
        int c = is64 ? (int)p64[ne + e] : p32[ne + e];   // col (destination)
        atomicAdd(&g_deg[c], 1);
    }
}

// --- coalesced 3-phase exclusive scan over g_deg -> g_off/g_cur ---
__global__ void scanA_kernel(int n) {
    int i    = blockIdx.x * 256 + threadIdx.x;
    int lane = threadIdx.x & 31, w = threadIdx.x >> 5;
    int v = (i < n) ? g_deg[i] : 0;
    int s = v;
#pragma unroll
    for (int o = 1; o < 32; o <<= 1) {
        int t = __shfl_up_sync(0xffffffffu, s, o);
        if (lane >= o) s += t;
    }
    __shared__ int ws[8], wo[8];
    if (lane == 31) ws[w] = s;
    __syncthreads();
    if (threadIdx.x == 0) {
        int run = 0;
#pragma unroll
        for (int k = 0; k < 8; k++) { wo[k] = run; run += ws[k]; }
        g_bsum[blockIdx.x] = run;
    }
    __syncthreads();
    if (i < n) g_off[i] = s - v + wo[w];   // block-local exclusive
}

__global__ void scanB_kernel(int nb, int n) {
    __shared__ int s[1024];
    int tid = threadIdx.x;
    int v = (tid < nb) ? g_bsum[tid] : 0;
    s[tid] = v;
    __syncthreads();
    for (int o = 1; o < 1024; o <<= 1) {
        int t = (tid >= o) ? s[tid - o] : 0;
        __syncthreads();
        s[tid] += t;
        __syncthreads();
    }
    if (tid < nb) g_bpre[tid] = s[tid] - v;
    if (tid == 1023) g_off[n] = s[1023];
}

__global__ void scanC_kernel(int n) {
    int i = blockIdx.x * 256 + threadIdx.x;
    if (i < n) {
        int o = g_off[i] + g_bpre[blockIdx.x];
        g_off[i] = o;
        g_cur[i] = o;
    }
}

__global__ void scatter_kernel(const void* __restrict__ ei, int ne) {
    const long long* p64 = (const long long*)ei;
    const int*       p32 = (const int*)ei;
    int is64 = g_is64;
    for (int e = blockIdx.x * blockDim.x + threadIdx.x; e < ne; e += gridDim.x * blockDim.x) {
        int c = is64 ? (int)p64[ne + e] : p32[ne + e];
        int r = is64 ? (int)p64[e]      : p32[e];
        int p = atomicAdd(&g_cur[c], 1);
        g_adj[p] = r;
    }
}

// -------------------------------------------------------- front-end (fused) ---
// x = relu(feat @ Win + bin); Q = 1+elu(x@Wq+bq); K = 1+elu(x@Wk+bk); V = x@Wv+bv
// M0 = K outer V (fp16); hidden = hopwise[0] * V
__global__ void feat_kernel(const float* __restrict__ feat,
                            const float* __restrict__ Win, const float* __restrict__ bin,
                            const float* __restrict__ Wq,  const float* __restrict__ bq,
                            const float* __restrict__ Wk,  const float* __restrict__ bk,
                            const float* __restrict__ Wv,  const float* __restrict__ bv,
                            const float* __restrict__ hopwise,
                            float* __restrict__ out, int n) {
    __shared__ float sWin[FIN * C];
    __shared__ float sWq[C * C], sWk[C * C], sWv[C * D];
    __shared__ float sb[3 * C + D];
    __shared__ float sx [8][FIN];
    __shared__ float sxs[8][C];

    int tid = threadIdx.x;
    for (int i = tid; i < FIN * C; i += 256) sWin[i] = Win[i];
    for (int i = tid; i < C * C;   i += 256) { sWq[i] = Wq[i]; sWk[i] = Wk[i]; }
    for (int i = tid; i < C * D;   i += 256) sWv[i] = Wv[i];
    if (tid < C) { sb[tid] = bin[tid]; sb[C + tid] = bq[tid]; sb[2 * C + tid] = bk[tid]; }
    if (tid < D) sb[3 * C + tid] = bv[tid];
    __syncthreads();

    int w = tid >> 5, lane = tid & 31;
    int node = blockIdx.x * 8 + w;
    if (node >= n) return;

    ((float4*)sx[w])[lane] = ((const float4*)feat)[node * (FIN / 4) + lane];
    __syncwarp();

    float acc = sb[lane];
#pragma unroll 8
    for (int i = 0; i < FIN; i++) acc = fmaf(sx[w][i], sWin[i * C + lane], acc);
    float x = fmaxf(acc, 0.f);
    sxs[w][lane] = x;
    __syncwarp();

    float qz = sb[C + lane], kz = sb[2 * C + lane];
    float vz = (lane < D) ? sb[3 * C + lane] : 0.f;
#pragma unroll
    for (int i = 0; i < C; i++) {
        float xi = sxs[w][i];
        qz = fmaf(xi, sWq[i * C + lane], qz);
        kz = fmaf(xi, sWk[i * C + lane], kz);
        if (lane < D) vz = fmaf(xi, sWv[i * D + lane], vz);
    }
    float q = (qz > 0.f) ? 1.f + qz : expf(qz);  // 1 + elu
    float k = (kz > 0.f) ? 1.f + kz : expf(kz);

    g_Q[node * C + lane]       = q;
    g_Kbuf[0][node * C + lane] = k;

    if (lane < D) out[node * D + lane] = hopwise[0] * vz;

    // M0[node][i=lane][j] = k * V[j], fp16; row = 512 halfs, lane owns halfs [lane*16, +16)
    float vv[16];
#pragma unroll
    for (int j = 0; j < 16; j++) vv[j] = __shfl_sync(0xffffffffu, vz, j);

    __half2 h[8];
#pragma unroll
    for (int j = 0; j < 8; j++) h[j] = __floats2half2_rn(k * vv[2 * j], k * vv[2 * j + 1]);

    uint4* dst = (uint4*)&g_Mh[0][(size_t)node * 512 + lane * 16];
    uint4 u0, u1;
    u0.x = *(unsigned*)&h[0]; u0.y = *(unsigned*)&h[1];
    u0.z = *(unsigned*)&h[2]; u0.w = *(unsigned*)&h[3];
    u1.x = *(unsigned*)&h[4]; u1.y = *(unsigned*)&h[5];
    u1.z = *(unsigned*)&h[6]; u1.w = *(unsigned*)&h[7];
    dst[0] = u0; dst[1] = u1;
}

// ------------------------------------------------------------- fused hop ------
// per dst node c: M_new = sum M_old[r], K_new = sum K_old[r]; then from the
// fp32 register accumulators: H = Q.M_new, Cden = Q.K_new + CST,
// hidden += hw * H/Cden. 128 threads: thread t owns halfs 4t..4t+3 of the row.
__global__ void hop_kernel(float* __restrict__ out,
                           const float* __restrict__ hopwise,
                           int hop, int src, int writeM) {
    const uint2* __restrict__ Mold = (const uint2*)g_Mh[src];
    uint2*       __restrict__ Mnew = (uint2*)g_Mh[src ^ 1];
    const float* __restrict__ Kold = g_Kbuf[src];
    float*       __restrict__ Knew = g_Kbuf[src ^ 1];

    int c = blockIdx.x;
    int t = threadIdx.x;            // 0..127
    int start = g_off[c], end = g_off[c + 1];

    float4 acc = make_float4(0.f, 0.f, 0.f, 0.f);
    float  kacc = 0.f;
    for (int e = start; e < end; e++) {
        int r = g_adj[e];
        uint2 u = Mold[(size_t)r * 128 + t];
        __half2 a = *reinterpret_cast<const __half2*>(&u.x);
        __half2 b = *reinterpret_cast<const __half2*>(&u.y);
        float2 fa = __half22float2(a);
        float2 fb = __half22float2(b);
        acc.x += fa.x; acc.y += fa.y; acc.z += fb.x; acc.w += fb.y;
        if (t < 32) kacc += Kold[r * 32 + t];
    }
    if (writeM) {
        __half2 ha = __floats2half2_rn(acc.x, acc.y);
        __half2 hb = __floats2half2_rn(acc.z, acc.w);
        uint2 o; o.x = *(unsigned*)&ha; o.y = *(unsigned*)&hb;
        Mnew[(size_t)c * 128 + t] = o;
        if (t < 32) Knew[c * 32 + t] = kacc;
    }

    // H partials from fp32 acc: i = t>>2 (row of M), jgroup = t&3 (cols 4g..4g+3)
    int i = t >> 2;
    float qi = g_Q[c * 32 + i];
    float h0 = qi * acc.x, h1 = qi * acc.y, h2 = qi * acc.z, h3 = qi * acc.w;
#pragma unroll
    for (int off = 4; off <= 16; off <<= 1) {
        h0 += __shfl_xor_sync(0xffffffffu, h0, off);
        h1 += __shfl_xor_sync(0xffffffffu, h1, off);
        h2 += __shfl_xor_sync(0xffffffffu, h2, off);
        h3 += __shfl_xor_sync(0xffffffffu, h3, off);
    }

    __shared__ float sH[4][4][4];   // [warp][jgroup][k]
    __shared__ float sC;
    int lane = t & 31, w = t >> 5;
    if (lane < 4) { sH[w][lane][0] = h0; sH[w][lane][1] = h1; sH[w][lane][2] = h2; sH[w][lane][3] = h3; }
    if (t < 32) {  // warp 0 holds kacc
        float cp = g_Q[c * 32 + t] * kacc;
#pragma unroll
        for (int off = 16; off >= 1; off >>= 1) cp += __shfl_xor_sync(0xffffffffu, cp, off);
        if (t == 0) sC = cp;
    }
    __syncthreads();

    if (t < 16) {
        float H = sH[0][t >> 2][t & 3] + sH[1][t >> 2][t & 3]
                + sH[2][t >> 2][t & 3] + sH[3][t >> 2][t & 3];
        out[c * 16 + t] += hopwise[hop + 1] * H / (sC + CST);
    }
}

// ------------------------------------------------------------------ launch ----
extern "C" void kernel_launch(void* const* d_in, const int* in_sizes, int n_in,
                              void* d_out, int out_size) {
    const float* feat    = (const float*)d_in[0];
    const void*  ei      = d_in[1];
    const float* Win     = (const float*)d_in[2];
    const float* bin     = (const float*)d_in[3];
    const float* Wq      = (const float*)d_in[4];
    const float* bq      = (const float*)d_in[5];
    const float* Wk      = (const float*)d_in[6];
    const float* bk      = (const float*)d_in[7];
    const float* Wv      = (const float*)d_in[8];
    const float* bv      = (const float*)d_in[9];
    const float* hopwise = (const float*)d_in[10];
    float*       out     = (float*)d_out;

    int n  = in_sizes[0] / FIN;   // 100000
    int ne = in_sizes[1] / 2;     // 800000
    int nb = (n + 255) / 256;     // 391

    // detect int32 vs int64 edge indices, then CSR build (by destination)
    detect_kernel<<<1, 1>>>(ei, n);
    zero_deg_kernel<<<256, 256>>>(n);
    count_kernel<<<1024, 256>>>(ei, ne);
    scanA_kernel<<<nb, 256>>>(n);
    scanB_kernel<<<1, 1024>>>(nb, n);
    scanC_kernel<<<nb, 256>>>(n);
    scatter_kernel<<<1024, 256>>>(ei, ne);

    // front-end: x, Q, K0, V, M0, hidden init
    feat_kernel<<<(n + 7) / 8, 256>>>(feat, Win, bin, Wq, bq, Wk, bk, Wv, bv,
                                      hopwise, out, n);

    // 3 hops; last hop skips M/K writeback
    int src = 0;
    for (int hop = 0; hop < 3; hop++) {
        hop_kernel<<<n, 128>>>(out, hopwise, hop, src, hop < 2 ? 1 : 0);
        src ^= 1;
    }
}

// round 4
// speedup vs baseline: 1.5360x; 1.0031x over previous
#include <cuda_runtime.h>
#include <cuda_fp16.h>
#include <math.h>

#define NN   100000
#define NE   800000
#define FIN  128
#define C    32
#define D    16
#define CST  1e-5f

// ---------- persistent scratch (device globals; no allocation allowed) ----------
__device__ float  g_Q[NN * C];                  // 12.8 MB
__device__ __half g_Kh[2][NN * C];              // 2 x 6.4 MB
__device__ __half g_Mh[2][NN * C * D];          // 2 x 102.4 MB (row = 512 halfs)
__device__ int    g_deg[NN];
__device__ int    g_off[NN + 1];
__device__ int    g_cur[NN];
__device__ int    g_adj[NE];
__device__ int    g_bsum[1024];
__device__ int    g_bpre[1024];
__device__ int    g_is64;

// ------------------------------------------------- edge dtype detection -------
// int64 edge data: first 16 int64 reads all land in [0, n). int32 data read as
// int64 has the NEXT index in the high word -> out of range w.h.p.
__global__ void detect_kernel(const void* __restrict__ ei, int n) {
    const long long* p = (const long long*)ei;
    int ok = 1;
    for (int i = 0; i < 16; i++) {
        long long v = p[i];
        if (v < 0 || v >= (long long)n) ok = 0;
    }
    g_is64 = ok;
}

// ---------------------------------------------------------------- CSR build ---
__global__ void zero_deg_kernel(int n) {
    for (int i = blockIdx.x * blockDim.x + threadIdx.x; i < n; i += gridDim.x * blockDim.x)
        g_deg[i] = 0;
}

__global__ void count_kernel(const void* __restrict__ ei, int ne) {
    const long long* p64 = (const long long*)ei;
    const int*       p32 = (const int*)ei;
    int is64 = g_is64;
    for (int e = blockIdx.x * blockDim.x + threadIdx.x; e < ne; e += gridDim.x * blockDim.x) {
        int c = is64 ? (int)p64[ne + e] : p32[ne + e];   // col (destination)
        atomicAdd(&g_deg[c], 1);
    }
}

// --- coalesced 3-phase exclusive scan over g_deg -> g_off/g_cur ---
__global__ void scanA_kernel(int n) {
    int i    = blockIdx.x * 256 + threadIdx.x;
    int lane = threadIdx.x & 31, w = threadIdx.x >> 5;
    int v = (i < n) ? g_deg[i] : 0;
    int s = v;
#pragma unroll
    for (int o = 1; o < 32; o <<= 1) {
        int t = __shfl_up_sync(0xffffffffu, s, o);
        if (lane >= o) s += t;
    }
    __shared__ int ws[8], wo[8];
    if (lane == 31) ws[w] = s;
    __syncthreads();
    if (threadIdx.x == 0) {
        int run = 0;
#pragma unroll
        for (int k = 0; k < 8; k++) { wo[k] = run; run += ws[k]; }
        g_bsum[blockIdx.x] = run;
    }
    __syncthreads();
    if (i < n) g_off[i] = s - v + wo[w];   // block-local exclusive
}

__global__ void scanB_kernel(int nb, int n) {
    __shared__ int s[1024];
    int tid = threadIdx.x;
    int v = (tid < nb) ? g_bsum[tid] : 0;
    s[tid] = v;
    __syncthreads();
    for (int o = 1; o < 1024; o <<= 1) {
        int t = (tid >= o) ? s[tid - o] : 0;
        __syncthreads();
        s[tid] += t;
        __syncthreads();
    }
    if (tid < nb) g_bpre[tid] = s[tid] - v;
    if (tid == 1023) g_off[n] = s[1023];
}

__global__ void scanC_kernel(int n) {
    int i = blockIdx.x * 256 + threadIdx.x;
    if (i < n) {
        int o = g_off[i] + g_bpre[blockIdx.x];
        g_off[i] = o;
        g_cur[i] = o;
    }
}

__global__ void scatter_kernel(const void* __restrict__ ei, int ne) {
    const long long* p64 = (const long long*)ei;
    const int*       p32 = (const int*)ei;
    int is64 = g_is64;
    for (int e = blockIdx.x * blockDim.x + threadIdx.x; e < ne; e += gridDim.x * blockDim.x) {
        int c = is64 ? (int)p64[ne + e] : p32[ne + e];
        int r = is64 ? (int)p64[e]      : p32[e];
        int p = atomicAdd(&g_cur[c], 1);
        g_adj[p] = r;
    }
}

// -------------------------------------------------------- front-end (fused) ---
// x = relu(feat @ Win + bin); Q = 1+elu(x@Wq+bq); K = 1+elu(x@Wk+bk); V = x@Wv+bv
// M0 = K outer V (fp16); hidden = hopwise[0] * V
__global__ void feat_kernel(const float* __restrict__ feat,
                            const float* __restrict__ Win, const float* __restrict__ bin,
                            const float* __restrict__ Wq,  const float* __restrict__ bq,
                            const float* __restrict__ Wk,  const float* __restrict__ bk,
                            const float* __restrict__ Wv,  const float* __restrict__ bv,
                            const float* __restrict__ hopwise,
                            float* __restrict__ out, int n) {
    __shared__ float sWin[FIN * C];
    __shared__ float sWq[C * C], sWk[C * C], sWv[C * D];
    __shared__ float sb[3 * C + D];
    __shared__ float sx [8][FIN];
    __shared__ float sxs[8][C];

    int tid = threadIdx.x;
    for (int i = tid; i < FIN * C; i += 256) sWin[i] = Win[i];
    for (int i = tid; i < C * C;   i += 256) { sWq[i] = Wq[i]; sWk[i] = Wk[i]; }
    for (int i = tid; i < C * D;   i += 256) sWv[i] = Wv[i];
    if (tid < C) { sb[tid] = bin[tid]; sb[C + tid] = bq[tid]; sb[2 * C + tid] = bk[tid]; }
    if (tid < D) sb[3 * C + tid] = bv[tid];
    __syncthreads();

    int w = tid >> 5, lane = tid & 31;
    int node = blockIdx.x * 8 + w;
    if (node >= n) return;

    ((float4*)sx[w])[lane] = ((const float4*)feat)[node * (FIN / 4) + lane];
    __syncwarp();

    float acc = sb[lane];
#pragma unroll 8
    for (int i = 0; i < FIN; i++) acc = fmaf(sx[w][i], sWin[i * C + lane], acc);
    float x = fmaxf(acc, 0.f);
    sxs[w][lane] = x;
    __syncwarp();

    float qz = sb[C + lane], kz = sb[2 * C + lane];
    float vz = (lane < D) ? sb[3 * C + lane] : 0.f;
#pragma unroll
    for (int i = 0; i < C; i++) {
        float xi = sxs[w][i];
        qz = fmaf(xi, sWq[i * C + lane], qz);
        kz = fmaf(xi, sWk[i * C + lane], kz);
        if (lane < D) vz = fmaf(xi, sWv[i * D + lane], vz);
    }
    float q = (qz > 0.f) ? 1.f + qz : expf(qz);  // 1 + elu
    float k = (kz > 0.f) ? 1.f + kz : expf(kz);

    g_Q[node * C + lane]    = q;
    g_Kh[0][node * C + lane] = __float2half_rn(k);

    if (lane < D) out[node * D + lane] = hopwise[0] * vz;

    // M0[node][i=lane][j] = k * V[j], fp16; row = 512 halfs, lane owns halfs [lane*16, +16)
    float vv[16];
#pragma unroll
    for (int j = 0; j < 16; j++) vv[j] = __shfl_sync(0xffffffffu, vz, j);

    __half2 h[8];
#pragma unroll
    for (int j = 0; j < 8; j++) h[j] = __floats2half2_rn(k * vv[2 * j], k * vv[2 * j + 1]);

    uint4* dst = (uint4*)&g_Mh[0][(size_t)node * 512 + lane * 16];
    uint4 u0, u1;
    u0.x = *(unsigned*)&h[0]; u0.y = *(unsigned*)&h[1];
    u0.z = *(unsigned*)&h[2]; u0.w = *(unsigned*)&h[3];
    u1.x = *(unsigned*)&h[4]; u1.y = *(unsigned*)&h[5];
    u1.z = *(unsigned*)&h[6]; u1.w = *(unsigned*)&h[7];
    dst[0] = u0; dst[1] = u1;
}

// ------------------------------------------------------------- fused hop ------
// per dst node c: M_new = sum M_old[r], K_new = sum K_old[r]; then from the
// fp32 register accumulators: H = Q.M_new, Cden = Q.K_new + CST,
// hidden += hw * H/Cden. 128 threads: thread t owns halfs 4t..4t+3 of the row.
// M_new/K_new stored with streaming hint (__stcs) so the M_old gather keeps L2.
__global__ void hop_kernel(float* __restrict__ out,
                           const float* __restrict__ hopwise,
                           int hop, int src, int writeM) {
    const uint2*  __restrict__ Mold = (const uint2*)g_Mh[src];
    uint2*        __restrict__ Mnew = (uint2*)g_Mh[src ^ 1];
    const __half* __restrict__ Kold = g_Kh[src];
    __half*       __restrict__ Knew = g_Kh[src ^ 1];

    int c = blockIdx.x;
    int t = threadIdx.x;            // 0..127
    int start = g_off[c], end = g_off[c + 1];

    float4 acc = make_float4(0.f, 0.f, 0.f, 0.f);
    float  kacc = 0.f;
    for (int e = start; e < end; e++) {
        int r = g_adj[e];
        uint2 u = Mold[(size_t)r * 128 + t];
        __half2 a = *reinterpret_cast<const __half2*>(&u.x);
        __half2 b = *reinterpret_cast<const __half2*>(&u.y);
        float2 fa = __half22float2(a);
        float2 fb = __half22float2(b);
        acc.x += fa.x; acc.y += fa.y; acc.z += fb.x; acc.w += fb.y;
        if (t < 32) kacc += __half2float(Kold[r * 32 + t]);
    }
    if (writeM) {
        __half2 ha = __floats2half2_rn(acc.x, acc.y);
        __half2 hb = __floats2half2_rn(acc.z, acc.w);
        uint2 o; o.x = *(unsigned*)&ha; o.y = *(unsigned*)&hb;
        __stcs(&Mnew[(size_t)c * 128 + t], o);
        if (t < 32) {
            __half hk = __float2half_rn(kacc);
            __stcs((unsigned short*)&Knew[c * 32 + t], *(unsigned short*)&hk);
        }
    }

    // H partials from fp32 acc: i = t>>2 (row of M), jgroup = t&3 (cols 4g..4g+3)
    int i = t >> 2;
    float qi = g_Q[c * 32 + i];
    float h0 = qi * acc.x, h1 = qi * acc.y, h2 = qi * acc.z, h3 = qi * acc.w;
#pragma unroll
    for (int off = 4; off <= 16; off <<= 1) {
        h0 += __shfl_xor_sync(0xffffffffu, h0, off);
        h1 += __shfl_xor_sync(0xffffffffu, h1, off);
        h2 += __shfl_xor_sync(0xffffffffu, h2, off);
        h3 += __shfl_xor_sync(0xffffffffu, h3, off);
    }

    __shared__ float sH[4][4][4];   // [warp][jgroup][k]
    __shared__ float sC;
    int lane = t & 31, w = t >> 5;
    if (lane < 4) { sH[w][lane][0] = h0; sH[w][lane][1] = h1; sH[w][lane][2] = h2; sH[w][lane][3] = h3; }
    if (t < 32) {  // warp 0 holds kacc
        float cp = g_Q[c * 32 + t] * kacc;
#pragma unroll
        for (int off = 16; off >= 1; off >>= 1) cp += __shfl_xor_sync(0xffffffffu, cp, off);
        if (t == 0) sC = cp;
    }
    __syncthreads();

    if (t < 16) {
        float H = sH[0][t >> 2][t & 3] + sH[1][t >> 2][t & 3]
                + sH[2][t >> 2][t & 3] + sH[3][t >> 2][t & 3];
        out[c * 16 + t] += hopwise[hop + 1] * H / (sC + CST);
    }
}

// ------------------------------------------------------------------ launch ----
extern "C" void kernel_launch(void* const* d_in, const int* in_sizes, int n_in,
                              void* d_out, int out_size) {
    const float* feat    = (const float*)d_in[0];
    const void*  ei      = d_in[1];
    const float* Win     = (const float*)d_in[2];
    const float* bin     = (const float*)d_in[3];
    const float* Wq      = (const float*)d_in[4];
    const float* bq      = (const float*)d_in[5];
    const float* Wk      = (const float*)d_in[6];
    const float* bk      = (const float*)d_in[7];
    const float* Wv      = (const float*)d_in[8];
    const float* bv      = (const float*)d_in[9];
    const float* hopwise = (const float*)d_in[10];
    float*       out     = (float*)d_out;

    int n  = in_sizes[0] / FIN;   // 100000
    int ne = in_sizes[1] / 2;     // 800000
    int nb = (n + 255) / 256;     // 391

    // detect int32 vs int64 edge indices, then CSR build (by destination)
    detect_kernel<<<1, 1>>>(ei, n);
    zero_deg_kernel<<<256, 256>>>(n);
    count_kernel<<<1024, 256>>>(ei, ne);
    scanA_kernel<<<nb, 256>>>(n);
    scanB_kernel<<<1, 1024>>>(nb, n);
    scanC_kernel<<<nb, 256>>>(n);
    scatter_kernel<<<1024, 256>>>(ei, ne);

    // front-end: x, Q, K0, V, M0, hidden init
    feat_kernel<<<(n + 7) / 8, 256>>>(feat, Win, bin, Wq, bq, Wk, bk, Wv, bv,
                                      hopwise, out, n);

    // 3 hops; last hop skips M/K writeback
    int src = 0;
    for (int hop = 0; hop < 3; hop++) {
        hop_kernel<<<n, 128>>>(out, hopwise, hop, src, hop < 2 ? 1 : 0);
        src ^= 1;
    }
}

// round 5
// speedup vs baseline: 1.5591x; 1.0151x over previous
#include <cuda_runtime.h>
#include <cuda_fp16.h>
#include <math.h>

#define NN   100000
#define NE   800000
#define FIN  128
#define C    32
#define D    16
#define CST  1e-5f

// ---------- persistent scratch (device globals; no allocation allowed) ----------
__device__ float  g_Q[NN * C];                  // 12.8 MB
__device__ __half g_KV0[NN * 64];               // 12.8 MB: per node 32 K halfs + 16 V halfs + 16 pad (128B row)
__device__ __half g_Kh[2][NN * C];              // 2 x 6.4 MB  (K1, K2)
__device__ __half g_Mh[2][NN * C * D];          // 2 x 102.4 MB (M1, M2; row = 512 halfs)
__device__ int    g_deg[NN];
__device__ int    g_off[NN + 1];
__device__ int    g_cur[NN];
__device__ int    g_adj[NE];
__device__ int    g_bsum[1024];
__device__ int    g_bpre[1024];
__device__ int    g_is64;

// ------------------------------------------------- edge dtype detection -------
__global__ void detect_kernel(const void* __restrict__ ei, int n) {
    const long long* p = (const long long*)ei;
    int ok = 1;
    for (int i = 0; i < 16; i++) {
        long long v = p[i];
        if (v < 0 || v >= (long long)n) ok = 0;
    }
    g_is64 = ok;
}

// ---------------------------------------------------------------- CSR build ---
__global__ void zero_deg_kernel(int n) {
    for (int i = blockIdx.x * blockDim.x + threadIdx.x; i < n; i += gridDim.x * blockDim.x)
        g_deg[i] = 0;
}

__global__ void count_kernel(const void* __restrict__ ei, int ne) {
    const long long* p64 = (const long long*)ei;
    const int*       p32 = (const int*)ei;
    int is64 = g_is64;
    for (int e = blockIdx.x * blockDim.x + threadIdx.x; e < ne; e += gridDim.x * blockDim.x) {
        int c = is64 ? (int)p64[ne + e] : p32[ne + e];   // col (destination)
        atomicAdd(&g_deg[c], 1);
    }
}

__global__ void scanA_kernel(int n) {
    int i    = blockIdx.x * 256 + threadIdx.x;
    int lane = threadIdx.x & 31, w = threadIdx.x >> 5;
    int v = (i < n) ? g_deg[i] : 0;
    int s = v;
#pragma unroll
    for (int o = 1; o < 32; o <<= 1) {
        int t = __shfl_up_sync(0xffffffffu, s, o);
        if (lane >= o) s += t;
    }
    __shared__ int ws[8], wo[8];
    if (lane == 31) ws[w] = s;
    __syncthreads();
    if (threadIdx.x == 0) {
        int run = 0;
#pragma unroll
        for (int k = 0; k < 8; k++) { wo[k] = run; run += ws[k]; }
        g_bsum[blockIdx.x] = run;
    }
    __syncthreads();
    if (i < n) g_off[i] = s - v + wo[w];
}

__global__ void scanB_kernel(int nb, int n) {
    __shared__ int s[1024];
    int tid = threadIdx.x;
    int v = (tid < nb) ? g_bsum[tid] : 0;
    s[tid] = v;
    __syncthreads();
    for (int o = 1; o < 1024; o <<= 1) {
        int t = (tid >= o) ? s[tid - o] : 0;
        __syncthreads();
        s[tid] += t;
        __syncthreads();
    }
    if (tid < nb) g_bpre[tid] = s[tid] - v;
    if (tid == 1023) g_off[n] = s[1023];
}

__global__ void scanC_kernel(int n) {
    int i = blockIdx.x * 256 + threadIdx.x;
    if (i < n) {
        int o = g_off[i] + g_bpre[blockIdx.x];
        g_off[i] = o;
        g_cur[i] = o;
    }
}

__global__ void scatter_kernel(const void* __restrict__ ei, int ne) {
    const long long* p64 = (const long long*)ei;
    const int*       p32 = (const int*)ei;
    int is64 = g_is64;
    for (int e = blockIdx.x * blockDim.x + threadIdx.x; e < ne; e += gridDim.x * blockDim.x) {
        int c = is64 ? (int)p64[ne + e] : p32[ne + e];
        int r = is64 ? (int)p64[e]      : p32[e];
        int p = atomicAdd(&g_cur[c], 1);
        g_adj[p] = r;
    }
}

// -------------------------------------------------------- front-end (fused) ---
// x = relu(feat@Win+bin); Q = 1+elu(x@Wq+bq); K = 1+elu(x@Wk+bk); V = x@Wv+bv
// Store Q fp32, (K|V) packed fp16 per node (128B row). NO M0 materialization.
__global__ void feat_kernel(const float* __restrict__ feat,
                            const float* __restrict__ Win, const float* __restrict__ bin,
                            const float* __restrict__ Wq,  const float* __restrict__ bq,
                            const float* __restrict__ Wk,  const float* __restrict__ bk,
                            const float* __restrict__ Wv,  const float* __restrict__ bv,
                            const float* __restrict__ hopwise,
                            float* __restrict__ out, int n) {
    __shared__ float sWin[FIN * C];
    __shared__ float sWq[C * C], sWk[C * C], sWv[C * D];
    __shared__ float sb[3 * C + D];
    __shared__ float sx [8][FIN];
    __shared__ float sxs[8][C];

    int tid = threadIdx.x;
    for (int i = tid; i < FIN * C; i += 256) sWin[i] = Win[i];
    for (int i = tid; i < C * C;   i += 256) { sWq[i] = Wq[i]; sWk[i] = Wk[i]; }
    for (int i = tid; i < C * D;   i += 256) sWv[i] = Wv[i];
    if (tid < C) { sb[tid] = bin[tid]; sb[C + tid] = bq[tid]; sb[2 * C + tid] = bk[tid]; }
    if (tid < D) sb[3 * C + tid] = bv[tid];
    __syncthreads();

    int w = tid >> 5, lane = tid & 31;
    int node = blockIdx.x * 8 + w;
    if (node >= n) return;

    ((float4*)sx[w])[lane] = ((const float4*)feat)[node * (FIN / 4) + lane];
    __syncwarp();

    float acc = sb[lane];
#pragma unroll 8
    for (int i = 0; i < FIN; i++) acc = fmaf(sx[w][i], sWin[i * C + lane], acc);
    float x = fmaxf(acc, 0.f);
    sxs[w][lane] = x;
    __syncwarp();

    float qz = sb[C + lane], kz = sb[2 * C + lane];
    float vz = (lane < D) ? sb[3 * C + lane] : 0.f;
#pragma unroll
    for (int i = 0; i < C; i++) {
        float xi = sxs[w][i];
        qz = fmaf(xi, sWq[i * C + lane], qz);
        kz = fmaf(xi, sWk[i * C + lane], kz);
        if (lane < D) vz = fmaf(xi, sWv[i * D + lane], vz);
    }
    float q = (qz > 0.f) ? 1.f + qz : expf(qz);  // 1 + elu
    float k = (kz > 0.f) ? 1.f + kz : expf(kz);

    g_Q[node * C + lane] = q;

    __half* kv = &g_KV0[node * 64];
    kv[lane] = __float2half_rn(k);                 // K halfs [0,32)
    if (lane < D) kv[32 + lane] = __float2half_rn(vz);  // V halfs [32,48)
    if (lane < 16) kv[48 + lane] = __half(0.f);    // pad

    if (lane < D) out[node * D + lane] = hopwise[0] * vz;
}

// --------------------------------------------------------------- H/C epilogue -
// shared by hop kernels: acc (float4, thread t covers M[i=t>>2][4g..4g+3]) and
// kacc (threads 0..31) -> hidden[c] += hw * (Q.M)/(Q.K + CST)
__device__ __forceinline__ void hc_epilogue(float* __restrict__ out, int c,
                                            float hw, float4 acc, float kacc,
                                            int t) {
    int i = t >> 2;
    float qi = g_Q[c * 32 + i];
    float h0 = qi * acc.x, h1 = qi * acc.y, h2 = qi * acc.z, h3 = qi * acc.w;
#pragma unroll
    for (int off = 4; off <= 16; off <<= 1) {
        h0 += __shfl_xor_sync(0xffffffffu, h0, off);
        h1 += __shfl_xor_sync(0xffffffffu, h1, off);
        h2 += __shfl_xor_sync(0xffffffffu, h2, off);
        h3 += __shfl_xor_sync(0xffffffffu, h3, off);
    }
    __shared__ float sH[4][4][4];
    __shared__ float sC;
    int lane = t & 31, w = t >> 5;
    if (lane < 4) { sH[w][lane][0] = h0; sH[w][lane][1] = h1; sH[w][lane][2] = h2; sH[w][lane][3] = h3; }
    if (t < 32) {
        float cp = g_Q[c * 32 + t] * kacc;
#pragma unroll
        for (int off = 16; off >= 1; off >>= 1) cp += __shfl_xor_sync(0xffffffffu, cp, off);
        if (t == 0) sC = cp;
    }
    __syncthreads();
    if (t < 16) {
        float H = sH[0][t >> 2][t & 3] + sH[1][t >> 2][t & 3]
                + sH[2][t >> 2][t & 3] + sH[3][t >> 2][t & 3];
        out[c * 16 + t] += hw * H / (sC + CST);
    }
}

// ------------------------------------------------------------- hop 1 (rank-1) -
// M1[c] = sum_{r->c} K0[r] (x) V0[r] built from 96B factor rows (L2-resident),
// K1[c] = sum K0[r]. Writes M1 (fp16) + K1; H1/C1 from fp32 accumulators.
__global__ void hop1_kernel(float* __restrict__ out,
                            const float* __restrict__ hopwise) {
    int c = blockIdx.x;
    int t = threadIdx.x;            // 0..127
    int i = t >> 2, g = t & 3;
    int start = g_off[c], end = g_off[c + 1];

    float4 acc = make_float4(0.f, 0.f, 0.f, 0.f);
    float  kacc = 0.f;

    int e = start;
    for (; e + 1 < end; e += 2) {
        int r0 = g_adj[e], r1 = g_adj[e + 1];
        const __half* kv0 = &g_KV0[r0 * 64];
        const __half* kv1 = &g_KV0[r1 * 64];
        float k0 = __half2float(kv0[i]);
        float k1 = __half2float(kv1[i]);
        uint2 uv0 = *(const uint2*)&kv0[32 + 4 * g];
        uint2 uv1 = *(const uint2*)&kv1[32 + 4 * g];
        float2 a0 = __half22float2(*(const __half2*)&uv0.x);
        float2 b0 = __half22float2(*(const __half2*)&uv0.y);
        float2 a1 = __half22float2(*(const __half2*)&uv1.x);
        float2 b1 = __half22float2(*(const __half2*)&uv1.y);
        acc.x = fmaf(k0, a0.x, fmaf(k1, a1.x, acc.x));
        acc.y = fmaf(k0, a0.y, fmaf(k1, a1.y, acc.y));
        acc.z = fmaf(k0, b0.x, fmaf(k1, b1.x, acc.z));
        acc.w = fmaf(k0, b0.y, fmaf(k1, b1.y, acc.w));
        if (t < 32) kacc += __half2float(kv0[t]) + __half2float(kv1[t]);
    }
    if (e < end) {
        int r0 = g_adj[e];
        const __half* kv0 = &g_KV0[r0 * 64];
        float k0 = __half2float(kv0[i]);
        uint2 uv0 = *(const uint2*)&kv0[32 + 4 * g];
        float2 a0 = __half22float2(*(const __half2*)&uv0.x);
        float2 b0 = __half22float2(*(const __half2*)&uv0.y);
        acc.x = fmaf(k0, a0.x, acc.x);
        acc.y = fmaf(k0, a0.y, acc.y);
        acc.z = fmaf(k0, b0.x, acc.z);
        acc.w = fmaf(k0, b0.y, acc.w);
        if (t < 32) kacc += __half2float(kv0[t]);
    }

    // write M1, K1
    {
        __half2 ha = __floats2half2_rn(acc.x, acc.y);
        __half2 hb = __floats2half2_rn(acc.z, acc.w);
        uint2 o; o.x = *(unsigned*)&ha; o.y = *(unsigned*)&hb;
        __stcs(&((uint2*)g_Mh[0])[(size_t)c * 128 + t], o);
        if (t < 32) {
            __half hk = __float2half_rn(kacc);
            __stcs((unsigned short*)&g_Kh[0][c * 32 + t], *(unsigned short*)&hk);
        }
    }

    hc_epilogue(out, c, hopwise[1], acc, kacc, t);
}

// ------------------------------------------------------------- hops 2 & 3 -----
// Gather full M rows (fp16, 1KB) with 2-edge unroll for MLP.
__global__ void hop_kernel(float* __restrict__ out,
                           const float* __restrict__ hopwise,
                           int hop, int src, int writeM) {
    const uint2*  __restrict__ Mold = (const uint2*)g_Mh[src];
    uint2*        __restrict__ Mnew = (uint2*)g_Mh[src ^ 1];
    const __half* __restrict__ Kold = g_Kh[src];
    __half*       __restrict__ Knew = g_Kh[src ^ 1];

    int c = blockIdx.x;
    int t = threadIdx.x;            // 0..127
    int start = g_off[c], end = g_off[c + 1];

    float4 acc = make_float4(0.f, 0.f, 0.f, 0.f);
    float  kacc = 0.f;

    int e = start;
    for (; e + 1 < end; e += 2) {
        int r0 = g_adj[e], r1 = g_adj[e + 1];
        uint2 u0 = Mold[(size_t)r0 * 128 + t];
        uint2 u1 = Mold[(size_t)r1 * 128 + t];
        float2 a0 = __half22float2(*(const __half2*)&u0.x);
        float2 b0 = __half22float2(*(const __half2*)&u0.y);
        float2 a1 = __half22float2(*(const __half2*)&u1.x);
        float2 b1 = __half22float2(*(const __half2*)&u1.y);
        acc.x += a0.x + a1.x; acc.y += a0.y + a1.y;
        acc.z += b0.x + b1.x; acc.w += b0.y + b1.y;
        if (t < 32) kacc += __half2float(Kold[r0 * 32 + t]) + __half2float(Kold[r1 * 32 + t]);
    }
    if (e < end) {
        int r0 = g_adj[e];
        uint2 u0 = Mold[(size_t)r0 * 128 + t];
        float2 a0 = __half22float2(*(const __half2*)&u0.x);
        float2 b0 = __half22float2(*(const __half2*)&u0.y);
        acc.x += a0.x; acc.y += a0.y; acc.z += b0.x; acc.w += b0.y;
        if (t < 32) kacc += __half2float(Kold[r0 * 32 + t]);
    }

    if (writeM) {
        __half2 ha = __floats2half2_rn(acc.x, acc.y);
        __half2 hb = __floats2half2_rn(acc.z, acc.w);
        uint2 o; o.x = *(unsigned*)&ha; o.y = *(unsigned*)&hb;
        __stcs(&Mnew[(size_t)c * 128 + t], o);
        if (t < 32) {
            __half hk = __float2half_rn(kacc);
            __stcs((unsigned short*)&Knew[c * 32 + t], *(unsigned short*)&hk);
        }
    }

    hc_epilogue(out, c, hopwise[hop + 1], acc, kacc, t);
}

// ------------------------------------------------------------------ launch ----
extern "C" void kernel_launch(void* const* d_in, const int* in_sizes, int n_in,
                              void* d_out, int out_size) {
    const float* feat    = (const float*)d_in[0];
    const void*  ei      = d_in[1];
    const float* Win     = (const float*)d_in[2];
    const float* bin     = (const float*)d_in[3];
    const float* Wq      = (const float*)d_in[4];
    const float* bq      = (const float*)d_in[5];
    const float* Wk      = (const float*)d_in[6];
    const float* bk      = (const float*)d_in[7];
    const float* Wv      = (const float*)d_in[8];
    const float* bv      = (const float*)d_in[9];
    const float* hopwise = (const float*)d_in[10];
    float*       out     = (float*)d_out;

    int n  = in_sizes[0] / FIN;   // 100000
    int ne = in_sizes[1] / 2;     // 800000
    int nb = (n + 255) / 256;     // 391

    detect_kernel<<<1, 1>>>(ei, n);
    zero_deg_kernel<<<256, 256>>>(n);
    count_kernel<<<1024, 256>>>(ei, ne);
    scanA_kernel<<<nb, 256>>>(n);
    scanB_kernel<<<1, 1024>>>(nb, n);
    scanC_kernel<<<nb, 256>>>(n);
    scatter_kernel<<<1024, 256>>>(ei, ne);

    feat_kernel<<<(n + 7) / 8, 256>>>(feat, Win, bin, Wq, bq, Wk, bk, Wv, bv,
                                      hopwise, out, n);

    // hop1: rank-1 factors (K0,V0) -> M1,K1 + H1
    hop1_kernel<<<n, 128>>>(out, hopwise);
    // hop2: gather M1 -> M2,K2 + H2
    hop_kernel<<<n, 128>>>(out, hopwise, 1, 0, 1);
    // hop3: gather M2 -> H3 only
    hop_kernel<<<n, 128>>>(out, hopwise, 2, 1, 0);
}